// round 1
// baseline (speedup 1.0000x reference)
#include <cuda_runtime.h>
#include <math.h>
#include <stdint.h>

#define N_NODES 4096
#define N_EDGES 16384
#define D       64
#define BG      16
#define SLOPE   0.01f

// ---------------- device scratch (static globals: no allocation) ----------------
__device__ float g_We[(size_t)N_EDGES * D * D];   // 256 MB edge weight tensor
__device__ float g_he[N_EDGES * D];
__device__ float g_h[N_NODES * D];
__device__ float g_agg[N_NODES * D];
__device__ float g_deg[N_NODES];
__device__ float g_WihT[D * 3 * D];               // [k][g] transposed GRU weights
__device__ float g_WhhT[D * 3 * D];
__device__ float g_q[D];
__device__ float g_e[N_NODES];
__device__ float g_a[N_NODES];
__device__ float g_emax[BG];
__device__ float g_asum[BG];
__device__ float g_rpool[BG * D];

__device__ __forceinline__ float lrelu(float x) { return x >= 0.f ? x : SLOPE * x; }
__device__ __forceinline__ float sigm(float x)  { return 1.f / (1.f + expf(-x)); }

__device__ __forceinline__ void atomicMaxF(float* addr, float v) {
    int* ai = (int*)addr;
    int old = *ai;
    while (__int_as_float(old) < v) {
        int assumed = old;
        old = atomicCAS(ai, assumed, __float_as_int(v));
        if (old == assumed) break;
    }
}

// ---------------- prep kernels ----------------

__global__ void k_zero_deg() {
    int i = blockIdx.x * blockDim.x + threadIdx.x;
    if (i < N_NODES) g_deg[i] = 0.f;
}

__global__ void k_zero_agg() {
    int i = blockIdx.x * blockDim.x + threadIdx.x;
    if (i < N_NODES * D) g_agg[i] = 0.f;
}

// h0 = lrelu(x @ W0 + b0) ; thread per (n,f)
__global__ void k_node_init(const float* __restrict__ x,
                            const float* __restrict__ W0,
                            const float* __restrict__ b0) {
    int idx = blockIdx.x * blockDim.x + threadIdx.x;
    if (idx >= N_NODES * D) return;
    int n = idx >> 6, f = idx & 63;
    float acc = b0[f];
    acc += x[n * 3 + 0] * W0[0 * D + f];
    acc += x[n * 3 + 1] * W0[1 * D + f];
    acc += x[n * 3 + 2] * W0[2 * D + f];
    g_h[idx] = lrelu(acc);
}

// he = lrelu(edge_attr @ We1 + be1); also degree count
__global__ void k_edge_init(const float* __restrict__ ea,
                            const float* __restrict__ We1,
                            const float* __restrict__ be1,
                            const int* __restrict__ ei) {
    int idx = blockIdx.x * blockDim.x + threadIdx.x;
    if (idx >= N_EDGES * D) return;
    int e = idx >> 6, f = idx & 63;
    float acc = be1[f];
    acc += ea[e * 4 + 0] * We1[0 * D + f];
    acc += ea[e * 4 + 1] * We1[1 * D + f];
    acc += ea[e * 4 + 2] * We1[2 * D + f];
    acc += ea[e * 4 + 3] * We1[3 * D + f];
    g_he[idx] = lrelu(acc);
    if (f == 0) {
        int dst = ei[N_EDGES + e];
        atomicAdd(&g_deg[dst], 1.f);
    }
}

// transpose GRU weights: WihT[k*192+g] = Wih[g*64+k]
__global__ void k_transpose(const float* __restrict__ Wih,
                            const float* __restrict__ Whh) {
    int idx = blockIdx.x * blockDim.x + threadIdx.x;
    if (idx >= 3 * D * D) return;
    int g = idx >> 6, k = idx & 63;
    g_WihT[k * (3 * D) + g] = Wih[idx];
    g_WhhT[k * (3 * D) + g] = Whh[idx];
}

// W_e = he @ We2 + be2  -> [E, 4096]
// block tile: 64 edges x 128 cols, 256 threads; shared 48KB exactly.
__global__ void k_we_gemm(const float* __restrict__ We2,
                          const float* __restrict__ be2) {
    __shared__ float sW[D][128];      // 32 KB
    __shared__ float sHe[D][D];       // 16 KB
    int jbase = blockIdx.x * 128;
    int ebase = blockIdx.y * 64;
    int tid = threadIdx.x;

    for (int idx = tid; idx < D * 128; idx += 256) {
        int k = idx >> 7, jj = idx & 127;
        sW[k][jj] = We2[(size_t)k * 4096 + jbase + jj];
    }
    for (int idx = tid; idx < 64 * D; idx += 256) {
        int el = idx >> 6, k = idx & 63;
        sHe[el][k] = g_he[(ebase + el) * D + k];
    }
    __syncthreads();

    int jl = tid & 31;      // 32 j-lanes, 4 cols (float4) each
    int eg = tid >> 5;      // 8 edge groups, 8 edges each
    float acc[8][4];
#pragma unroll
    for (int i = 0; i < 8; i++) { acc[i][0] = acc[i][1] = acc[i][2] = acc[i][3] = 0.f; }

#pragma unroll 8
    for (int k = 0; k < D; k++) {
        float4 w = *(const float4*)&sW[k][jl * 4];
#pragma unroll
        for (int i = 0; i < 8; i++) {
            float hv = sHe[eg * 8 + i][k];
            acc[i][0] += hv * w.x;
            acc[i][1] += hv * w.y;
            acc[i][2] += hv * w.z;
            acc[i][3] += hv * w.w;
        }
    }

    int j = jbase + jl * 4;
    float4 b4 = *(const float4*)&be2[j];
#pragma unroll
    for (int i = 0; i < 8; i++) {
        int el = ebase + eg * 8 + i;
        float4 o;
        o.x = acc[i][0] + b4.x;
        o.y = acc[i][1] + b4.y;
        o.z = acc[i][2] + b4.z;
        o.w = acc[i][3] + b4.w;
        *(float4*)&g_We[(size_t)el * 4096 + j] = o;
    }
}

// ---------------- loop kernels ----------------

// msg[e,f] = sum_d h[src[e],d] * W_e[e,d,f]; scatter-add to agg[dst]
// 4 edges per 256-thread block
__global__ void k_msg(const int* __restrict__ ei) {
    int le = threadIdx.x >> 6;
    int f  = threadIdx.x & 63;
    int e  = blockIdx.x * 4 + le;
    __shared__ float sx[4][D];
    int src = ei[e];
    int dst = ei[N_EDGES + e];
    sx[le][f] = g_h[src * D + f];
    __syncthreads();
    const float* W = g_We + (size_t)e * 4096;
    float acc = 0.f;
#pragma unroll
    for (int d = 0; d < D; d++) acc += sx[le][d] * W[d * D + f];
    atomicAdd(&g_agg[dst * D + f], acc);
}

// node update: m = lrelu(agg/deg + h@root + conv_b); GRU cell; h <- h_new
// 4 nodes per 256-thread block
__global__ void k_node_update(const float* __restrict__ root,
                              const float* __restrict__ conv_b,
                              const float* __restrict__ bih,
                              const float* __restrict__ bhh) {
    int ln = threadIdx.x >> 6;
    int f  = threadIdx.x & 63;
    int n  = blockIdx.x * 4 + ln;
    __shared__ float sh[4][D];
    __shared__ float sm[4][D];
    sh[ln][f] = g_h[n * D + f];
    __syncthreads();

    float invd = 1.f / fmaxf(g_deg[n], 1.f);
    float acc = g_agg[n * D + f] * invd + conv_b[f];
#pragma unroll 8
    for (int d = 0; d < D; d++) acc += sh[ln][d] * root[d * D + f];
    sm[ln][f] = lrelu(acc);
    __syncthreads();

    float gi_r = bih[f], gi_z = bih[D + f], gi_n = bih[2 * D + f];
    float gh_r = bhh[f], gh_z = bhh[D + f], gh_n = bhh[2 * D + f];
#pragma unroll 8
    for (int k = 0; k < D; k++) {
        float mk = sm[ln][k];
        float hk = sh[ln][k];
        const float* wi = &g_WihT[k * (3 * D)];
        const float* wh = &g_WhhT[k * (3 * D)];
        gi_r += mk * wi[f];
        gi_z += mk * wi[D + f];
        gi_n += mk * wi[2 * D + f];
        gh_r += hk * wh[f];
        gh_z += hk * wh[D + f];
        gh_n += hk * wh[2 * D + f];
    }
    float r  = sigm(gi_r + gh_r);
    float z  = sigm(gi_z + gh_z);
    float nn = tanhf(gi_n + r * gh_n);
    g_h[n * D + f] = (1.f - z) * nn + z * sh[ln][f];
}

// ---------------- set2set + head ----------------

// one block: compute q from LSTM biases (state is all-zero, one step),
// init emax/asum/rpool
__global__ void k_s2s_init(const float* __restrict__ lbih,
                           const float* __restrict__ lbhh) {
    int t = threadIdx.x;
    if (t < D) {
        float gi = lbih[t]           + lbhh[t];
        float gf = lbih[D + t]       + lbhh[D + t];
        float gg = lbih[2 * D + t]   + lbhh[2 * D + t];
        float go = lbih[3 * D + t]   + lbhh[3 * D + t];
        (void)gf; // cl_prev = 0, so f-gate contributes nothing
        float cl = sigm(gi) * tanhf(gg);
        g_q[t] = sigm(go) * tanhf(cl);
    }
    if (t < BG) { g_emax[t] = -3.4e38f; g_asum[t] = 0.f; }
    for (int i = t; i < BG * D; i += blockDim.x) g_rpool[i] = 0.f;
}

// e[n] = dot(h[n], q); per-graph max (warp per node)
__global__ void k_dot(const int* __restrict__ batch) {
    int lane = threadIdx.x & 31;
    int warp = threadIdx.x >> 5;
    int n = blockIdx.x * 8 + warp;
    if (n >= N_NODES) return;
    float v = g_h[n * D + lane] * g_q[lane] + g_h[n * D + 32 + lane] * g_q[32 + lane];
#pragma unroll
    for (int o = 16; o > 0; o >>= 1) v += __shfl_down_sync(0xFFFFFFFFu, v, o);
    if (lane == 0) {
        g_e[n] = v;
        atomicMaxF(&g_emax[batch[n]], v);
    }
}

__global__ void k_exp(const int* __restrict__ batch) {
    int n = blockIdx.x * blockDim.x + threadIdx.x;
    if (n >= N_NODES) return;
    int g = batch[n];
    float a = expf(g_e[n] - g_emax[g]);
    g_a[n] = a;
    atomicAdd(&g_asum[g], a);
}

__global__ void k_pool(const int* __restrict__ batch) {
    int idx = blockIdx.x * blockDim.x + threadIdx.x;
    if (idx >= N_NODES * D) return;
    int n = idx >> 6, f = idx & 63;
    int g = batch[n];
    float w = g_a[n] / g_asum[g];
    atomicAdd(&g_rpool[g * D + f], w * g_h[idx]);
}

// out[b][c] = q . Wout[0:64, c] + rpool[b] . Wout[64:128, c] + bout[c]
__global__ void k_out(const float* __restrict__ Wout,
                      const float* __restrict__ bout,
                      float* __restrict__ out) {
    int t = threadIdx.x;
    if (t >= BG * 2) return;
    int b = t >> 1, c = t & 1;
    float acc = bout[c];
#pragma unroll 8
    for (int j = 0; j < D; j++) {
        acc += g_q[j] * Wout[j * 2 + c];
        acc += g_rpool[b * D + j] * Wout[(D + j) * 2 + c];
    }
    out[b * 2 + c] = acc;
}

// ---------------- launch ----------------

extern "C" void kernel_launch(void* const* d_in, const int* in_sizes, int n_in,
                              void* d_out, int out_size) {
    const float* x      = (const float*)d_in[0];
    const float* ea     = (const float*)d_in[1];
    const int*   ei     = (const int*)d_in[2];
    const int*   batch  = (const int*)d_in[3];
    const float* W0     = (const float*)d_in[4];
    const float* b0     = (const float*)d_in[5];
    const float* We1    = (const float*)d_in[6];
    const float* be1    = (const float*)d_in[7];
    const float* We2    = (const float*)d_in[8];
    const float* be2    = (const float*)d_in[9];
    const float* root   = (const float*)d_in[10];
    const float* conv_b = (const float*)d_in[11];
    const float* Wih    = (const float*)d_in[12];
    const float* Whh    = (const float*)d_in[13];
    const float* bih    = (const float*)d_in[14];
    const float* bhh    = (const float*)d_in[15];
    const float* lWih   = (const float*)d_in[16];
    const float* lWhh   = (const float*)d_in[17];
    const float* lbih   = (const float*)d_in[18];
    const float* lbhh   = (const float*)d_in[19];
    const float* Wout   = (const float*)d_in[20];
    const float* bout   = (const float*)d_in[21];
    float* out = (float*)d_out;
    (void)lWih; (void)lWhh; (void)in_sizes; (void)n_in; (void)out_size;

    // prep
    k_zero_deg<<<(N_NODES + 255) / 256, 256>>>();
    k_node_init<<<(N_NODES * D) / 256, 256>>>(x, W0, b0);
    k_edge_init<<<(N_EDGES * D) / 256, 256>>>(ea, We1, be1, ei);
    k_transpose<<<(3 * D * D + 255) / 256, 256>>>(Wih, Whh);
    {
        dim3 grid(4096 / 128, N_EDGES / 64);
        k_we_gemm<<<grid, 256>>>(We2, be2);
    }

    // 6 message-passing + GRU iterations
    for (int it = 0; it < 6; it++) {
        k_zero_agg<<<(N_NODES * D) / 256, 256>>>();
        k_msg<<<N_EDGES / 4, 256>>>(ei);
        k_node_update<<<N_NODES / 4, 256>>>(root, conv_b, bih, bhh);
    }

    // set2set + output head
    k_s2s_init<<<1, 256>>>(lbih, lbhh);
    k_dot<<<N_NODES / 8, 256>>>(batch);
    k_exp<<<(N_NODES + 255) / 256, 256>>>(batch);
    k_pool<<<(N_NODES * D) / 256, 256>>>(batch);
    k_out<<<1, 64>>>(Wout, bout, out);
}

// round 2
// speedup vs baseline: 1.0997x; 1.0997x over previous
#include <cuda_runtime.h>
#include <cuda_fp16.h>
#include <math.h>
#include <stdint.h>

#define N_NODES 4096
#define N_EDGES 16384
#define D       64
#define BG      16
#define SLOPE   0.01f

// ---------------- device scratch (static globals: no allocation) ----------------
__device__ __half g_We_h[(size_t)N_EDGES * D * D];  // 128 MB fp16 edge weights
__device__ float g_he[N_EDGES * D];
__device__ float g_h[N_NODES * D];
__device__ float g_agg[N_NODES * D];
__device__ float g_deg[N_NODES];
__device__ float g_WihT[D * 3 * D];
__device__ float g_WhhT[D * 3 * D];
__device__ float g_q[D];
__device__ float g_e[N_NODES];
__device__ float g_a[N_NODES];
__device__ float g_emax[BG];
__device__ float g_asum[BG];
__device__ float g_rpool[BG * D];

__device__ __forceinline__ float lrelu(float x) { return x >= 0.f ? x : SLOPE * x; }
__device__ __forceinline__ float sigm(float x)  { return 1.f / (1.f + expf(-x)); }

__device__ __forceinline__ uint64_t ffma2(uint64_t a, uint64_t b, uint64_t c) {
    uint64_t d;
    asm("fma.rn.f32x2 %0, %1, %2, %3;" : "=l"(d) : "l"(a), "l"(b), "l"(c));
    return d;
}
__device__ __forceinline__ uint64_t pack2(float x) {
    uint64_t d;
    asm("mov.b64 %0, {%1, %1};" : "=l"(d) : "r"(__float_as_uint(x)));
    return d;
}

__device__ __forceinline__ void atomicMaxF(float* addr, float v) {
    int* ai = (int*)addr;
    int old = *ai;
    while (__int_as_float(old) < v) {
        int assumed = old;
        old = atomicCAS(ai, assumed, __float_as_int(v));
        if (old == assumed) break;
    }
}

// ---------------- prep kernels ----------------

__global__ void k_zero_deg() {
    int i = blockIdx.x * blockDim.x + threadIdx.x;
    if (i < N_NODES) g_deg[i] = 0.f;
}

__global__ void k_zero_agg() {
    int i = blockIdx.x * blockDim.x + threadIdx.x;
    if (i < N_NODES * D) g_agg[i] = 0.f;
}

__global__ void k_node_init(const float* __restrict__ x,
                            const float* __restrict__ W0,
                            const float* __restrict__ b0) {
    int idx = blockIdx.x * blockDim.x + threadIdx.x;
    if (idx >= N_NODES * D) return;
    int n = idx >> 6, f = idx & 63;
    float acc = b0[f];
    acc += x[n * 3 + 0] * W0[0 * D + f];
    acc += x[n * 3 + 1] * W0[1 * D + f];
    acc += x[n * 3 + 2] * W0[2 * D + f];
    g_h[idx] = lrelu(acc);
}

__global__ void k_edge_init(const float* __restrict__ ea,
                            const float* __restrict__ We1,
                            const float* __restrict__ be1,
                            const int* __restrict__ ei) {
    int idx = blockIdx.x * blockDim.x + threadIdx.x;
    if (idx >= N_EDGES * D) return;
    int e = idx >> 6, f = idx & 63;
    float acc = be1[f];
    acc += ea[e * 4 + 0] * We1[0 * D + f];
    acc += ea[e * 4 + 1] * We1[1 * D + f];
    acc += ea[e * 4 + 2] * We1[2 * D + f];
    acc += ea[e * 4 + 3] * We1[3 * D + f];
    g_he[idx] = lrelu(acc);
    if (f == 0) {
        int dst = ei[N_EDGES + e];
        atomicAdd(&g_deg[dst], 1.f);
    }
}

__global__ void k_transpose(const float* __restrict__ Wih,
                            const float* __restrict__ Whh) {
    int idx = blockIdx.x * blockDim.x + threadIdx.x;
    if (idx >= 3 * D * D) return;
    int g = idx >> 6, k = idx & 63;
    g_WihT[k * (3 * D) + g] = Wih[idx];
    g_WhhT[k * (3 * D) + g] = Whh[idx];
}

// W_e = he @ We2 + be2 -> fp16 [E, 4096]
// Tile: 64 edges x 128 cols, 256 threads.
// Thread map: eg = tid>>4 (4 edges each), jl = tid&15 (8 cols each).
// Inner loop uses packed fp32x2 FMA (2 FMA/instr, full fp32 precision).
__global__ void k_we_gemm(const float* __restrict__ We2,
                          const float* __restrict__ be2) {
    __shared__ float sW[D][128];   // 32 KB
    __shared__ float sHe[D][D];    // 16 KB
    int jbase = blockIdx.x * 128;
    int ebase = blockIdx.y * 64;
    int tid = threadIdx.x;

    for (int idx = tid; idx < D * 128; idx += 256) {
        int k = idx >> 7, jj = idx & 127;
        sW[k][jj] = We2[(size_t)k * 4096 + jbase + jj];
    }
    for (int idx = tid; idx < 64 * D; idx += 256) {
        int el = idx >> 6, k = idx & 63;
        sHe[el][k] = g_he[(ebase + el) * D + k];
    }
    __syncthreads();

    int eg = tid >> 4;   // 0..15: warp covers only 2 eg values -> broadcast LDS
    int jl = tid & 15;   // 0..15: 8 contiguous cols each

    uint64_t acc[4][4];
#pragma unroll
    for (int i = 0; i < 4; i++)
#pragma unroll
        for (int p = 0; p < 4; p++) acc[i][p] = 0ull;

#pragma unroll 4
    for (int k = 0; k < D; k++) {
        const uint64_t* wp = (const uint64_t*)&sW[k][jl * 8];
        uint64_t w0 = wp[0], w1 = wp[1], w2 = wp[2], w3 = wp[3];
#pragma unroll
        for (int i = 0; i < 4; i++) {
            uint64_t hv2 = pack2(sHe[eg * 4 + i][k]);
            acc[i][0] = ffma2(hv2, w0, acc[i][0]);
            acc[i][1] = ffma2(hv2, w1, acc[i][1]);
            acc[i][2] = ffma2(hv2, w2, acc[i][2]);
            acc[i][3] = ffma2(hv2, w3, acc[i][3]);
        }
    }

    float bj[8];
    *(float4*)&bj[0] = *(const float4*)&be2[jbase + jl * 8];
    *(float4*)&bj[4] = *(const float4*)&be2[jbase + jl * 8 + 4];

#pragma unroll
    for (int i = 0; i < 4; i++) {
        int el = ebase + eg * 4 + i;
        uint4 ov;
        __half2* hp = (__half2*)&ov;
#pragma unroll
        for (int p = 0; p < 4; p++) {
            float2 v = *(float2*)&acc[i][p];
            hp[p] = __floats2half2_rn(v.x + bj[2 * p], v.y + bj[2 * p + 1]);
        }
        *(uint4*)&g_We_h[(size_t)el * 4096 + jbase + jl * 8] = ov;
    }
}

// ---------------- loop kernels ----------------

// msg[e,f] = sum_d h[src[e],d] * W_e[e,d,f] (fp16 W, fp32 accum)
// 8 edges per 256-thread block; 32 lanes per edge, each owning a half2 col pair.
__global__ void k_msg(const int* __restrict__ ei) {
    int le = threadIdx.x >> 5;
    int lane = threadIdx.x & 31;
    int e = blockIdx.x * 8 + le;
    __shared__ float sx[8][D];
    int src = ei[e];
    int dst = ei[N_EDGES + e];
    sx[le][lane] = g_h[src * D + lane];
    sx[le][lane + 32] = g_h[src * D + 32 + lane];
    __syncthreads();

    const __half2* __restrict__ W = (const __half2*)(g_We_h + (size_t)e * 4096);
    float ax = 0.f, ay = 0.f;
#pragma unroll 16
    for (int d = 0; d < D; d++) {
        float hv = sx[le][d];
        float2 w = __half22float2(W[d * 32 + lane]);
        ax += hv * w.x;
        ay += hv * w.y;
    }
    atomicAdd(&g_agg[dst * D + 2 * lane], ax);
    atomicAdd(&g_agg[dst * D + 2 * lane + 1], ay);
}

// node update: m = lrelu(agg/deg + h@root + conv_b); GRU cell; h <- h_new
__global__ void k_node_update(const float* __restrict__ root,
                              const float* __restrict__ conv_b,
                              const float* __restrict__ bih,
                              const float* __restrict__ bhh) {
    int ln = threadIdx.x >> 6;
    int f  = threadIdx.x & 63;
    int n  = blockIdx.x * 4 + ln;
    __shared__ float sh[4][D];
    __shared__ float sm[4][D];
    sh[ln][f] = g_h[n * D + f];
    __syncthreads();

    float invd = 1.f / fmaxf(g_deg[n], 1.f);
    float acc = g_agg[n * D + f] * invd + conv_b[f];
#pragma unroll 8
    for (int d = 0; d < D; d++) acc += sh[ln][d] * root[d * D + f];
    sm[ln][f] = lrelu(acc);
    __syncthreads();

    float gi_r = bih[f], gi_z = bih[D + f], gi_n = bih[2 * D + f];
    float gh_r = bhh[f], gh_z = bhh[D + f], gh_n = bhh[2 * D + f];
#pragma unroll 8
    for (int k = 0; k < D; k++) {
        float mk = sm[ln][k];
        float hk = sh[ln][k];
        const float* wi = &g_WihT[k * (3 * D)];
        const float* wh = &g_WhhT[k * (3 * D)];
        gi_r += mk * wi[f];
        gi_z += mk * wi[D + f];
        gi_n += mk * wi[2 * D + f];
        gh_r += hk * wh[f];
        gh_z += hk * wh[D + f];
        gh_n += hk * wh[2 * D + f];
    }
    float r  = sigm(gi_r + gh_r);
    float z  = sigm(gi_z + gh_z);
    float nn = tanhf(gi_n + r * gh_n);
    g_h[n * D + f] = (1.f - z) * nn + z * sh[ln][f];
}

// ---------------- set2set + head ----------------

__global__ void k_s2s_init(const float* __restrict__ lbih,
                           const float* __restrict__ lbhh) {
    int t = threadIdx.x;
    if (t < D) {
        float gi = lbih[t]         + lbhh[t];
        float gg = lbih[2 * D + t] + lbhh[2 * D + t];
        float go = lbih[3 * D + t] + lbhh[3 * D + t];
        float cl = sigm(gi) * tanhf(gg);
        g_q[t] = sigm(go) * tanhf(cl);
    }
    if (t < BG) { g_emax[t] = -3.4e38f; g_asum[t] = 0.f; }
    for (int i = t; i < BG * D; i += blockDim.x) g_rpool[i] = 0.f;
}

__global__ void k_dot(const int* __restrict__ batch) {
    int lane = threadIdx.x & 31;
    int warp = threadIdx.x >> 5;
    int n = blockIdx.x * 8 + warp;
    if (n >= N_NODES) return;
    float v = g_h[n * D + lane] * g_q[lane] + g_h[n * D + 32 + lane] * g_q[32 + lane];
#pragma unroll
    for (int o = 16; o > 0; o >>= 1) v += __shfl_down_sync(0xFFFFFFFFu, v, o);
    if (lane == 0) {
        g_e[n] = v;
        atomicMaxF(&g_emax[batch[n]], v);
    }
}

__global__ void k_exp(const int* __restrict__ batch) {
    int n = blockIdx.x * blockDim.x + threadIdx.x;
    if (n >= N_NODES) return;
    int g = batch[n];
    float a = expf(g_e[n] - g_emax[g]);
    g_a[n] = a;
    atomicAdd(&g_asum[g], a);
}

__global__ void k_pool(const int* __restrict__ batch) {
    int idx = blockIdx.x * blockDim.x + threadIdx.x;
    if (idx >= N_NODES * D) return;
    int n = idx >> 6, f = idx & 63;
    int g = batch[n];
    float w = g_a[n] / g_asum[g];
    atomicAdd(&g_rpool[g * D + f], w * g_h[idx]);
}

__global__ void k_out(const float* __restrict__ Wout,
                      const float* __restrict__ bout,
                      float* __restrict__ out) {
    int t = threadIdx.x;
    if (t >= BG * 2) return;
    int b = t >> 1, c = t & 1;
    float acc = bout[c];
#pragma unroll 8
    for (int j = 0; j < D; j++) {
        acc += g_q[j] * Wout[j * 2 + c];
        acc += g_rpool[b * D + j] * Wout[(D + j) * 2 + c];
    }
    out[b * 2 + c] = acc;
}

// ---------------- launch ----------------

extern "C" void kernel_launch(void* const* d_in, const int* in_sizes, int n_in,
                              void* d_out, int out_size) {
    const float* x      = (const float*)d_in[0];
    const float* ea     = (const float*)d_in[1];
    const int*   ei     = (const int*)d_in[2];
    const int*   batch  = (const int*)d_in[3];
    const float* W0     = (const float*)d_in[4];
    const float* b0     = (const float*)d_in[5];
    const float* We1    = (const float*)d_in[6];
    const float* be1    = (const float*)d_in[7];
    const float* We2    = (const float*)d_in[8];
    const float* be2    = (const float*)d_in[9];
    const float* root   = (const float*)d_in[10];
    const float* conv_b = (const float*)d_in[11];
    const float* Wih    = (const float*)d_in[12];
    const float* Whh    = (const float*)d_in[13];
    const float* bih    = (const float*)d_in[14];
    const float* bhh    = (const float*)d_in[15];
    const float* lbih   = (const float*)d_in[18];
    const float* lbhh   = (const float*)d_in[19];
    const float* Wout   = (const float*)d_in[20];
    const float* bout   = (const float*)d_in[21];
    float* out = (float*)d_out;
    (void)in_sizes; (void)n_in; (void)out_size;

    k_zero_deg<<<(N_NODES + 255) / 256, 256>>>();
    k_node_init<<<(N_NODES * D) / 256, 256>>>(x, W0, b0);
    k_edge_init<<<(N_EDGES * D) / 256, 256>>>(ea, We1, be1, ei);
    k_transpose<<<(3 * D * D + 255) / 256, 256>>>(Wih, Whh);
    {
        dim3 grid(4096 / 128, N_EDGES / 64);
        k_we_gemm<<<grid, 256>>>(We2, be2);
    }

    for (int it = 0; it < 6; it++) {
        k_zero_agg<<<(N_NODES * D) / 256, 256>>>();
        k_msg<<<N_EDGES / 8, 256>>>(ei);
        k_node_update<<<N_NODES / 4, 256>>>(root, conv_b, bih, bhh);
    }

    k_s2s_init<<<1, 256>>>(lbih, lbhh);
    k_dot<<<N_NODES / 8, 256>>>(batch);
    k_exp<<<(N_NODES + 255) / 256, 256>>>(batch);
    k_pool<<<(N_NODES * D) / 256, 256>>>(batch);
    k_out<<<1, 64>>>(Wout, bout, out);
}

// round 3
// speedup vs baseline: 1.7139x; 1.5585x over previous
#include <cuda_runtime.h>
#include <cuda_fp16.h>
#include <math.h>
#include <stdint.h>

#define N_NODES 4096
#define N_EDGES 16384
#define D       64
#define BG      16
#define SLOPE   0.01f

// ---------------- device scratch (static globals: no allocation) ----------------
__device__ __half g_We_h[(size_t)N_EDGES * D * D];  // 128 MB fp16 edge weights
__device__ __half g_he_h[N_EDGES * D];              // fp16 edge hidden
__device__ __half g_We2T[4096 * D];                 // fp16 We2 transposed [n][k]
__device__ float g_h[N_NODES * D];
__device__ float g_agg[N_NODES * D];
__device__ float g_deg[N_NODES];
__device__ float g_Wi4[D * D * 4];                  // [k][f][{r,z,n,pad}]
__device__ float g_Wh4[D * D * 4];
__device__ float g_q[D];
__device__ float g_e[N_NODES];
__device__ float g_a[N_NODES];
__device__ float g_emax[BG];
__device__ float g_asum[BG];
__device__ float g_rpool[BG * D];

__device__ __forceinline__ float lrelu(float x) { return x >= 0.f ? x : SLOPE * x; }
__device__ __forceinline__ float sigm(float x)  { return 1.f / (1.f + expf(-x)); }

__device__ __forceinline__ void atomicMaxF(float* addr, float v) {
    int* ai = (int*)addr;
    int old = *ai;
    while (__int_as_float(old) < v) {
        int assumed = old;
        old = atomicCAS(ai, assumed, __float_as_int(v));
        if (old == assumed) break;
    }
}

__device__ __forceinline__ void mma16816(float c[4],
                                         uint32_t a0, uint32_t a1, uint32_t a2, uint32_t a3,
                                         uint32_t b0, uint32_t b1) {
    asm volatile(
        "mma.sync.aligned.m16n8k16.row.col.f32.f16.f16.f32 "
        "{%0,%1,%2,%3}, {%4,%5,%6,%7}, {%8,%9}, {%0,%1,%2,%3};"
        : "+f"(c[0]), "+f"(c[1]), "+f"(c[2]), "+f"(c[3])
        : "r"(a0), "r"(a1), "r"(a2), "r"(a3), "r"(b0), "r"(b1));
}

// ---------------- prep kernels ----------------

__global__ void k_zero_deg() {
    int i = blockIdx.x * blockDim.x + threadIdx.x;
    if (i < N_NODES) g_deg[i] = 0.f;
}

__global__ void k_zero_agg() {
    int i = blockIdx.x * blockDim.x + threadIdx.x;
    if (i < N_NODES * D) g_agg[i] = 0.f;
}

__global__ void k_node_init(const float* __restrict__ x,
                            const float* __restrict__ W0,
                            const float* __restrict__ b0) {
    int idx = blockIdx.x * blockDim.x + threadIdx.x;
    if (idx >= N_NODES * D) return;
    int n = idx >> 6, f = idx & 63;
    float acc = b0[f];
    acc += x[n * 3 + 0] * W0[0 * D + f];
    acc += x[n * 3 + 1] * W0[1 * D + f];
    acc += x[n * 3 + 2] * W0[2 * D + f];
    g_h[idx] = lrelu(acc);
}

__global__ void k_edge_init(const float* __restrict__ ea,
                            const float* __restrict__ We1,
                            const float* __restrict__ be1,
                            const int* __restrict__ ei) {
    int idx = blockIdx.x * blockDim.x + threadIdx.x;
    if (idx >= N_EDGES * D) return;
    int e = idx >> 6, f = idx & 63;
    float acc = be1[f];
    acc += ea[e * 4 + 0] * We1[0 * D + f];
    acc += ea[e * 4 + 1] * We1[1 * D + f];
    acc += ea[e * 4 + 2] * We1[2 * D + f];
    acc += ea[e * 4 + 3] * We1[3 * D + f];
    g_he_h[idx] = __float2half(lrelu(acc));
    if (f == 0) {
        int dst = ei[N_EDGES + e];
        atomicAdd(&g_deg[dst], 1.f);
    }
}

// We2T[n][k] = (half)We2[k][n]; coalesced read
__global__ void k_prep_we2t(const float* __restrict__ We2) {
    int idx = blockIdx.x * blockDim.x + threadIdx.x;
    if (idx >= 4096 * D) return;
    int n = idx & 4095, k = idx >> 12;
    g_We2T[n * D + k] = __float2half(We2[k * 4096 + n]);
}

// interleaved GRU weights: g_Wi4[k][f][g] = Wih[(g*64+f)*64+k]
__global__ void k_prep_gru(const float* __restrict__ Wih,
                           const float* __restrict__ Whh) {
    int idx = blockIdx.x * blockDim.x + threadIdx.x;
    if (idx >= D * D * 4) return;
    int gg = idx & 3, f = (idx >> 2) & 63, k = idx >> 8;
    float vi = 0.f, vh = 0.f;
    if (gg < 3) {
        vi = Wih[(gg * 64 + f) * 64 + k];
        vh = Whh[(gg * 64 + f) * 64 + k];
    }
    g_Wi4[idx] = vi;
    g_Wh4[idx] = vh;
}

// ---------------- tensor-core W_e GEMM ----------------
// W_e[e][j] = sum_k he[e][k] * We2[k][j] + be2[j], fp16 out.
// Block: 64 edges x 256 cols, 512 threads (16 warps, 4x4 warp grid).
__global__ void __launch_bounds__(512, 2) k_we_gemm(const float* __restrict__ be2) {
    __shared__ __half sA[64][72];     // he tile, padded (conflict-free)
    __shared__ __half sBT[256][72];   // We2T tile
    int nbase = blockIdx.x * 256;
    int ebase = blockIdx.y * 64;
    int tid = threadIdx.x;

    {
        int row = tid >> 3, ch = tid & 7;
        *(uint4*)&sA[row][ch * 8] = *(const uint4*)&g_he_h[(ebase + row) * D + ch * 8];
    }
#pragma unroll
    for (int i = 0; i < 4; i++) {
        int idx = tid + i * 512;
        int row = idx >> 3, ch = idx & 7;
        *(uint4*)&sBT[row][ch * 8] = *(const uint4*)&g_We2T[(nbase + row) * D + ch * 8];
    }
    __syncthreads();

    int warp = tid >> 5, lane = tid & 31;
    int wm = warp & 3, wn = warp >> 2;
    int g = lane >> 2, tig = lane & 3;

    float c[8][4];
#pragma unroll
    for (int j = 0; j < 8; j++) { c[j][0] = c[j][1] = c[j][2] = c[j][3] = 0.f; }

#pragma unroll
    for (int s = 0; s < 4; s++) {
        int r0 = wm * 16 + g;
        int k0 = s * 16 + 2 * tig;
        uint32_t a0 = *(uint32_t*)&sA[r0][k0];
        uint32_t a1 = *(uint32_t*)&sA[r0 + 8][k0];
        uint32_t a2 = *(uint32_t*)&sA[r0][k0 + 8];
        uint32_t a3 = *(uint32_t*)&sA[r0 + 8][k0 + 8];
#pragma unroll
        for (int j = 0; j < 8; j++) {
            int nn = wn * 64 + j * 8 + g;
            uint32_t b0 = *(uint32_t*)&sBT[nn][k0];
            uint32_t b1 = *(uint32_t*)&sBT[nn][k0 + 8];
            mma16816(c[j], a0, a1, a2, a3, b0, b1);
        }
    }

#pragma unroll
    for (int j = 0; j < 8; j++) {
        int col = nbase + wn * 64 + j * 8 + 2 * tig;
        float2 bb = *(const float2*)&be2[col];
        int e0 = ebase + wm * 16 + g;
        __half2 h01 = __floats2half2_rn(c[j][0] + bb.x, c[j][1] + bb.y);
        __half2 h23 = __floats2half2_rn(c[j][2] + bb.x, c[j][3] + bb.y);
        *(__half2*)&g_We_h[(size_t)e0 * 4096 + col] = h01;
        *(__half2*)&g_We_h[(size_t)(e0 + 8) * 4096 + col] = h23;
    }
}

// ---------------- loop kernels ----------------

// msg[e,f] = sum_d h[src[e],d] * W_e[e,d,f] (fp16 W, fp32 accum); scatter to agg
__global__ void k_msg(const int* __restrict__ ei) {
    int le = threadIdx.x >> 5;
    int lane = threadIdx.x & 31;
    int e = blockIdx.x * 8 + le;
    __shared__ float sx[8][D];
    int src = ei[e];
    int dst = ei[N_EDGES + e];
    sx[le][lane] = g_h[src * D + lane];
    sx[le][lane + 32] = g_h[src * D + 32 + lane];
    __syncthreads();

    const __half2* __restrict__ W = (const __half2*)(g_We_h + (size_t)e * 4096);
    float ax = 0.f, ay = 0.f;
#pragma unroll 16
    for (int d = 0; d < D; d++) {
        float hv = sx[le][d];
        float2 w = __half22float2(W[d * 32 + lane]);
        ax += hv * w.x;
        ay += hv * w.y;
    }
    atomicAdd(&g_agg[dst * D + 2 * lane], ax);
    atomicAdd(&g_agg[dst * D + 2 * lane + 1], ay);
}

// node update: m = lrelu(agg/deg + h@root + conv_b); GRU cell; h <- new; agg <- 0
// 256 blocks x 256 threads, 16 nodes/block, 4 nodes/thread.
__global__ void k_node_update(const float* __restrict__ root,
                              const float* __restrict__ conv_b,
                              const float* __restrict__ bih,
                              const float* __restrict__ bhh) {
    __shared__ float sh[16][D];
    __shared__ float sm[16][D];
    __shared__ float sroot[D][D];
    int nb = blockIdx.x * 16;
    int tid = threadIdx.x;
    int f = tid & 63, ng = tid >> 6;    // ng 0..3

#pragma unroll
    for (int i = 0; i < 4; i++) {
        int ln = ng + 4 * i;
        sh[ln][f] = g_h[(nb + ln) * D + f];
    }
#pragma unroll
    for (int i = 0; i < 16; i++) {
        int idx = tid + i * 256;
        sroot[idx >> 6][idx & 63] = root[idx];
    }
    __syncthreads();

    float cb = conv_b[f];
#pragma unroll
    for (int i = 0; i < 4; i++) {
        int ln = ng + 4 * i;
        int n = nb + ln;
        float invd = 1.f / fmaxf(g_deg[n], 1.f);
        float acc = g_agg[n * D + f] * invd + cb;
        g_agg[n * D + f] = 0.f;   // pre-zero for next iteration
#pragma unroll 8
        for (int d = 0; d < D; d++) acc += sh[ln][d] * sroot[d][f];
        sm[ln][f] = lrelu(acc);
    }
    __syncthreads();

    float gir[4], giz[4], gin[4], ghr[4], ghz[4], ghn[4];
    float bir = bih[f], biz = bih[D + f], bin = bih[2 * D + f];
    float bhr = bhh[f], bhz = bhh[D + f], bhn = bhh[2 * D + f];
#pragma unroll
    for (int i = 0; i < 4; i++) {
        gir[i] = bir; giz[i] = biz; gin[i] = bin;
        ghr[i] = bhr; ghz[i] = bhz; ghn[i] = bhn;
    }

#pragma unroll 4
    for (int k = 0; k < D; k++) {
        float4 wi = *(const float4*)&g_Wi4[(k * D + f) * 4];
        float4 wh = *(const float4*)&g_Wh4[(k * D + f) * 4];
#pragma unroll
        for (int i = 0; i < 4; i++) {
            int ln = ng + 4 * i;
            float mk = sm[ln][k];
            float hk = sh[ln][k];
            gir[i] += mk * wi.x; giz[i] += mk * wi.y; gin[i] += mk * wi.z;
            ghr[i] += hk * wh.x; ghz[i] += hk * wh.y; ghn[i] += hk * wh.z;
        }
    }

#pragma unroll
    for (int i = 0; i < 4; i++) {
        int ln = ng + 4 * i;
        float r  = sigm(gir[i] + ghr[i]);
        float z  = sigm(giz[i] + ghz[i]);
        float nn = tanhf(gin[i] + r * ghn[i]);
        g_h[(nb + ln) * D + f] = (1.f - z) * nn + z * sh[ln][f];
    }
}

// ---------------- set2set + head ----------------

__global__ void k_s2s_init(const float* __restrict__ lbih,
                           const float* __restrict__ lbhh) {
    int t = threadIdx.x;
    if (t < D) {
        float gi = lbih[t]         + lbhh[t];
        float gg = lbih[2 * D + t] + lbhh[2 * D + t];
        float go = lbih[3 * D + t] + lbhh[3 * D + t];
        float cl = sigm(gi) * tanhf(gg);
        g_q[t] = sigm(go) * tanhf(cl);
    }
    if (t < BG) { g_emax[t] = -3.4e38f; g_asum[t] = 0.f; }
    for (int i = t; i < BG * D; i += blockDim.x) g_rpool[i] = 0.f;
}

__global__ void k_dot(const int* __restrict__ batch) {
    int lane = threadIdx.x & 31;
    int warp = threadIdx.x >> 5;
    int n = blockIdx.x * 8 + warp;
    if (n >= N_NODES) return;
    float v = g_h[n * D + lane] * g_q[lane] + g_h[n * D + 32 + lane] * g_q[32 + lane];
#pragma unroll
    for (int o = 16; o > 0; o >>= 1) v += __shfl_down_sync(0xFFFFFFFFu, v, o);
    if (lane == 0) {
        g_e[n] = v;
        atomicMaxF(&g_emax[batch[n]], v);
    }
}

__global__ void k_exp(const int* __restrict__ batch) {
    int n = blockIdx.x * blockDim.x + threadIdx.x;
    if (n >= N_NODES) return;
    int g = batch[n];
    float a = expf(g_e[n] - g_emax[g]);
    g_a[n] = a;
    atomicAdd(&g_asum[g], a);
}

__global__ void k_pool(const int* __restrict__ batch) {
    int idx = blockIdx.x * blockDim.x + threadIdx.x;
    if (idx >= N_NODES * D) return;
    int n = idx >> 6, f = idx & 63;
    int g = batch[n];
    float w = g_a[n] / g_asum[g];
    atomicAdd(&g_rpool[g * D + f], w * g_h[idx]);
}

__global__ void k_out(const float* __restrict__ Wout,
                      const float* __restrict__ bout,
                      float* __restrict__ out) {
    int t = threadIdx.x;
    if (t >= BG * 2) return;
    int b = t >> 1, c = t & 1;
    float acc = bout[c];
#pragma unroll 8
    for (int j = 0; j < D; j++) {
        acc += g_q[j] * Wout[j * 2 + c];
        acc += g_rpool[b * D + j] * Wout[(D + j) * 2 + c];
    }
    out[b * 2 + c] = acc;
}

// ---------------- launch ----------------

extern "C" void kernel_launch(void* const* d_in, const int* in_sizes, int n_in,
                              void* d_out, int out_size) {
    const float* x      = (const float*)d_in[0];
    const float* ea     = (const float*)d_in[1];
    const int*   ei     = (const int*)d_in[2];
    const int*   batch  = (const int*)d_in[3];
    const float* W0     = (const float*)d_in[4];
    const float* b0     = (const float*)d_in[5];
    const float* We1    = (const float*)d_in[6];
    const float* be1    = (const float*)d_in[7];
    const float* We2    = (const float*)d_in[8];
    const float* be2    = (const float*)d_in[9];
    const float* root   = (const float*)d_in[10];
    const float* conv_b = (const float*)d_in[11];
    const float* Wih    = (const float*)d_in[12];
    const float* Whh    = (const float*)d_in[13];
    const float* bih    = (const float*)d_in[14];
    const float* bhh    = (const float*)d_in[15];
    const float* lbih   = (const float*)d_in[18];
    const float* lbhh   = (const float*)d_in[19];
    const float* Wout   = (const float*)d_in[20];
    const float* bout   = (const float*)d_in[21];
    float* out = (float*)d_out;
    (void)in_sizes; (void)n_in; (void)out_size;

    k_zero_deg<<<(N_NODES + 255) / 256, 256>>>();
    k_zero_agg<<<(N_NODES * D) / 256, 256>>>();
    k_node_init<<<(N_NODES * D) / 256, 256>>>(x, W0, b0);
    k_edge_init<<<(N_EDGES * D) / 256, 256>>>(ea, We1, be1, ei);
    k_prep_we2t<<<(4096 * D) / 256, 256>>>(We2);
    k_prep_gru<<<(D * D * 4) / 256, 256>>>(Wih, Whh);
    {
        dim3 grid(4096 / 256, N_EDGES / 64);
        k_we_gemm<<<grid, 512>>>(be2);
    }

    for (int it = 0; it < 6; it++) {
        k_msg<<<N_EDGES / 8, 256>>>(ei);
        k_node_update<<<N_NODES / 16, 256>>>(root, conv_b, bih, bhh);
    }

    k_s2s_init<<<1, 256>>>(lbih, lbhh);
    k_dot<<<N_NODES / 8, 256>>>(batch);
    k_exp<<<(N_NODES + 255) / 256, 256>>>(batch);
    k_pool<<<(N_NODES * D) / 256, 256>>>(batch);
    k_out<<<1, 64>>>(Wout, bout, out);
}